// round 10
// baseline (speedup 1.0000x reference)
#include <cuda_runtime.h>
#include <cuda_bf16.h>
#include <cstdint>

#define BB 128
#define SS 50
#define XX 128
#define HH 256
#define VV 10000
#define MM (BB*SS)     // 6400
#define NPAD 10240     // VV padded to N-tile multiple

// ---------------- device scratch (no allocs allowed in kernel_launch) ------
__device__ float g_xin[MM * HH];                         // input projection [b][t][j]
__device__ float g_WT[HH * HH];                          // W_hh transposed: [k][j]
// t-MAJOR: row m = t*128 + b ; [m][0:256]=hi, [256:512]=lo
__device__ __align__(16) __nv_bfloat16 g_A2[MM * 512];
__device__ __align__(16) __nv_bfloat16 g_B2[(size_t)NPAD * 512]; // split of W_aff
__device__ int g_prog[SS];                               // per-step producer arrivals

// ---------------- packed fp32x2 helpers --------------------------------------
__device__ __forceinline__ double dup2(float x) {
    double r; asm("mov.b64 %0, {%1, %1};" : "=d"(r) : "f"(x)); return r;
}
__device__ __forceinline__ double pk2(float lo, float hi) {
    double r; asm("mov.b64 %0, {%1, %2};" : "=d"(r) : "f"(lo), "f"(hi)); return r;
}
__device__ __forceinline__ float2 unpk(double d) {
    float2 f; asm("mov.b64 {%0, %1}, %2;" : "=f"(f.x), "=f"(f.y) : "d"(d)); return f;
}
__device__ __forceinline__ void ffma2(double& acc, double a, double b) {
    asm("fma.rn.f32x2 %0, %1, %2, %0;" : "+d"(acc) : "d"(a), "d"(b));
}
__device__ __forceinline__ double fadd2(double a, double b) {
    double r; asm("add.rn.f32x2 %0, %1, %2;" : "=d"(r) : "d"(a), "d"(b)); return r;
}

// ---------------- mma / smem helpers ------------------------------------------
__device__ __forceinline__ uint32_t smem_u32(const void* p) {
    uint32_t a;
    asm("{ .reg .u64 t; cvta.to.shared.u64 t, %1; cvt.u32.u64 %0, t; }" : "=r"(a) : "l"(p));
    return a;
}
__device__ __forceinline__ void cp_async16(uint32_t dst, const void* src) {
    asm volatile("cp.async.cg.shared.global [%0], [%1], 16;"
                 :: "r"(dst), "l"(src) : "memory");
}
__device__ __forceinline__ void ldsm4(uint32_t r[4], uint32_t addr) {
    asm volatile("ldmatrix.sync.aligned.m8n8.x4.shared.b16 {%0,%1,%2,%3}, [%4];"
                 : "=r"(r[0]), "=r"(r[1]), "=r"(r[2]), "=r"(r[3]) : "r"(addr));
}
__device__ __forceinline__ void mma16816(float c[4], const uint32_t a[4],
                                         uint32_t b0, uint32_t b1) {
    asm volatile(
        "mma.sync.aligned.m16n8k16.row.col.f32.bf16.bf16.f32 "
        "{%0,%1,%2,%3}, {%4,%5,%6,%7}, {%8,%9}, {%0,%1,%2,%3};"
        : "+f"(c[0]), "+f"(c[1]), "+f"(c[2]), "+f"(c[3])
        : "r"(a[0]), "r"(a[1]), "r"(a[2]), "r"(a[3]), "r"(b0), "r"(b1));
}
__device__ __forceinline__ int ld_acq(const int* p) {
    int v; asm volatile("ld.acquire.gpu.global.b32 %0, [%1];" : "=r"(v) : "l"(p)); return v;
}
__device__ __forceinline__ void red_release(int* p) {
    asm volatile("red.release.gpu.global.add.s32 [%0], %1;" :: "l"(p), "r"(1) : "memory");
}
#define SW128(x) ((x) ^ (((x) >> 3) & 0x70))

__device__ __forceinline__ void store_split(__nv_bfloat16* p, float v) {
    __nv_bfloat16 hi = __float2bfloat16(v);
    p[0]   = hi;
    p[256] = __float2bfloat16(v - __bfloat162float(hi));
}

// ============================================================================
// Kernel A (fused prep): embed+proj | split W_aff | transpose W_hh | zero prog
// ============================================================================
#define NB_EMB 400
#define NB_SPL 2560
#define NB_TRA 256
#define NB_PREP (NB_EMB + NB_SPL + NB_TRA)

__global__ void __launch_bounds__(256)
prep(const int* __restrict__ xraw,
     const float* __restrict__ emb,
     const float* __restrict__ W_ih,
     const float* __restrict__ b_ih,
     const float* __restrict__ b_hh,
     const float* __restrict__ W_hh,
     const float* __restrict__ Wa)
{
    const int bb = blockIdx.x;

    if (bb >= NB_EMB + NB_SPL) {                 // ---- transpose W_hh ----
        int idx = (bb - NB_EMB - NB_SPL) * 256 + threadIdx.x;  // 65536 elems
        int k = idx >> 8, j = idx & 255;
        g_WT[k * HH + j] = W_hh[j * HH + k];
        return;
    }
    if (bb >= NB_EMB) {                          // ---- split W_aff ----
        int idx = (bb - NB_EMB) * 256 + threadIdx.x;   // NPAD * 64
        int n  = idx >> 6;
        int k4 = (idx & 63) << 2;
        float4 w = make_float4(0.f, 0.f, 0.f, 0.f);
        if (n < VV) w = *(const float4*)(Wa + (size_t)n * 256 + k4);
        __nv_bfloat16* p = g_B2 + (size_t)n * 512 + k4;
        __nv_bfloat16 h0 = __float2bfloat16(w.x);
        __nv_bfloat16 h1 = __float2bfloat16(w.y);
        __nv_bfloat16 h2 = __float2bfloat16(w.z);
        __nv_bfloat16 h3 = __float2bfloat16(w.w);
        p[0] = h0; p[1] = h1; p[2] = h2; p[3] = h3;
        p[256] = __float2bfloat16(w.x - __bfloat162float(h0));
        p[257] = __float2bfloat16(w.y - __bfloat162float(h1));
        p[258] = __float2bfloat16(w.z - __bfloat162float(h2));
        p[259] = __float2bfloat16(w.w - __bfloat162float(h3));
        return;
    }

    // ---- embedding + input projection (16 rows per block) ----
    if (bb == 0 && threadIdx.x < SS) g_prog[threadIdx.x] = 0;   // reset progress

    __shared__ __align__(16) float se[16][XX];

    const bool is64 = ((xraw[1] | xraw[3] | xraw[5] | xraw[7] | xraw[9]) == 0) &&
                      ((xraw[0] | xraw[2] | xraw[4] | xraw[6] | xraw[8]) != 0);

    const int m0 = bb * 16;
    for (int i = threadIdx.x; i < 16 * (XX / 4); i += 256) {
        int r = i >> 5, c = i & 31;
        int m = m0 + r;
        int tok = is64 ? xraw[2 * m] : xraw[m];
        ((float4*)se[r])[c] = ((const float4*)(emb + (long long)tok * XX))[c];
    }
    __syncthreads();

    const int j = threadIdx.x;
    const float bias = b_ih[j] + b_hh[j];
    float acc[16];
#pragma unroll
    for (int r = 0; r < 16; r++) acc[r] = bias;

    const float* wr = W_ih + j * XX;
#pragma unroll 4
    for (int k = 0; k < XX; k += 4) {
        float4 w = *(const float4*)(wr + k);
#pragma unroll
        for (int r = 0; r < 16; r++) {
            float4 e = *(const float4*)&se[r][k];
            acc[r] = fmaf(w.x, e.x, fmaf(w.y, e.y, fmaf(w.z, e.z, fmaf(w.w, e.w, acc[r]))));
        }
    }
#pragma unroll
    for (int r = 0; r < 16; r++)
        g_xin[(m0 + r) * HH + j] = acc[r];
}

// ============================================================================
// FUSED kernel, cluster(4):
//   RNN producers live on bids 0..31 and 148..179: CLC placement for cluster
//   launches is (bid+142)%148 contiguous-modular, so bid b and b+148 share an
//   SM -> rnn pairs with rnn (32 SMs), gemm gets 116 clean SMs.
//   All other bids = GEMM consumers, t-major tiles (unchanged internals).
// Unified dynamic smem = 98304 -> 2 CTAs/SM.
// ============================================================================
#define RNN_W_F2   (128 * 64)            // float2: quarter of W
#define RNN_HB_F2  (2 * 4 * 256)         // [buf][rq][col]
#define TILE_BYTES 16384
#define STAGE_BYTES (2 * TILE_BYTES)
#define NSTAGE 3
#define SMEM_FUSED (NSTAGE * STAGE_BYTES)   // 98304 (rnn uses 80 KB subset)
#define NB_RNN 64
#define NT_N   (NPAD / 128)              // 80 n-tiles per timestep
#define NB_FUSED (NB_RNN + SS * NT_N)    // 64 + 4000 = 4064

__global__ void __launch_bounds__(256, 2) __cluster_dims__(4, 1, 1)
fused_rnn_gemm(const float* __restrict__ ba, float* __restrict__ C)
{
    extern __shared__ __align__(1024) char smem[];
    const int bid = blockIdx.x;
    const int tid = threadIdx.x;

    const bool is_rnn = (bid < 32) || (bid >= 148 && bid < 180);

    if (is_rnn) {
        // ==================== RNN producer (cluster-4) ========================
        const int rnn_id = (bid < 32) ? bid : (bid - 116);   // 0..63

        float2* wsp = (float2*)smem;            // [k2*64 + jl], k2=0..127
        float2* hb  = (float2*)smem + RNN_W_F2; // [(buf*4 + rq)*256 + col]
        const uint32_t hb_addr = smem_u32(hb);

        const int rq   = tid >> 6;              // rowpair 0..3
        const int jl   = tid & 63;
        const uint32_t rank = bid & 3;          // == rnn_id & 3 (148%4==0)
        const int jg   = rank * 64 + jl;        // global output column
        const int b0   = (rnn_id >> 2) * 8;     // 8 batch rows per cluster

        // fill W quarter: wsp[k2][jl] = (WT[2k2][jg], WT[2k2+1][jg])
        for (int i = tid; i < RNN_W_F2; i += 256) {
            int k2 = i >> 6, j = i & 63;
            int jgl = rank * 64 + j;
            wsp[i] = make_float2(g_WT[(2 * k2) * HH + jgl],
                                 g_WT[(2 * k2 + 1) * HH + jgl]);
        }
        // zero h buffer 0
        for (int i = tid; i < 4 * 256; i += 256) hb[i] = make_float2(0.f, 0.f);

        asm volatile("barrier.cluster.arrive.aligned;" ::: "memory");
        asm volatile("barrier.cluster.wait.aligned;" ::: "memory");

        const int r0 = b0 + 2 * rq;
        const float* x0p = g_xin + (size_t)r0 * SS * HH + jg;
        const float* x1p = g_xin + (size_t)(r0 + 1) * SS * HH + jg;
        // t-major A2: row m = t*BB + b
        __nv_bfloat16* a0p = g_A2 + (size_t)r0 * 512 + jg;
        __nv_bfloat16* a1p = g_A2 + (size_t)(r0 + 1) * 512 + jg;

        const float2* wp = wsp + jl;
        const uint32_t p1 = rank ^ 1, p2 = rank ^ 2, p3 = rank ^ 3;

        float xa = x0p[0], xb = x1p[0];   // prefetched x for step t
        int cur = 0;
        for (int t = 0; t < SS; ++t) {
            double acc_e = pk2(xa, xb);
            double acc_o = 0.0;
            if (t + 1 < SS) {             // prefetch next step's x early
                xa = x0p[(size_t)(t + 1) * HH];
                xb = x1p[(size_t)(t + 1) * HH];
            }

            const double2* hc = (const double2*)(hb + (cur * 4 + rq) * 256);
#pragma unroll 8
            for (int k2 = 0; k2 < 128; ++k2) {
                float2 wv  = wp[k2 * 64];
                double2 h2 = hc[k2];
                ffma2(acc_e, dup2(wv.x), h2.x);
                ffma2(acc_o, dup2(wv.y), h2.y);
            }

            float2 f = unpk(fadd2(acc_e, acc_o));
            float h0 = tanhf(f.x), h1 = tanhf(f.y);

            const int nxt = cur ^ 1;
            const long long hp = __double_as_longlong(pk2(h0, h1));
            uint32_t loc = hb_addr + (uint32_t)(((nxt * 4 + rq) * 256 + jg) * 8);
            asm volatile("st.shared.b64 [%0], %1;" :: "r"(loc), "l"(hp) : "memory");
            asm volatile(
                "{\n\t.reg .b32 ra;\n\t"
                "mapa.shared::cluster.u32 ra, %0, %1;\n\t"
                "st.shared::cluster.b64 [ra], %2;\n\t"
                "mapa.shared::cluster.u32 ra, %0, %3;\n\t"
                "st.shared::cluster.b64 [ra], %2;\n\t"
                "mapa.shared::cluster.u32 ra, %0, %4;\n\t"
                "st.shared::cluster.b64 [ra], %2;\n\t}"
                :: "r"(loc), "r"(p1), "l"(hp), "r"(p2), "r"(p3) : "memory");

            store_split(a0p + (size_t)t * (BB * 512), h0);
            store_split(a1p + (size_t)t * (BB * 512), h1);

            // cluster barrier establishes happens-before for ALL threads'
            // global stores; tid0's release-RMW publishes them gpu-wide.
            asm volatile("barrier.cluster.arrive.aligned;" ::: "memory");
            asm volatile("barrier.cluster.wait.aligned;" ::: "memory");
            if (tid == 0) red_release(&g_prog[t]);
            cur = nxt;
        }
        return;
    }

    // ======================= GEMM consumer ==================================
    const int gid = (bid < 148) ? (bid - 32) : (bid - 64);
    const int tT  = gid / NT_N;            // timestep tile (M-tile)
    const int bn  = (gid % NT_N) * 128;
    const int bm  = tT * 128;

    // wait for all 64 producers of step tT
    if (tid == 0) {
        while (ld_acq(&g_prog[tT]) < NB_RNN) __nanosleep(256);
    }
    __syncthreads();

    const uint32_t sb = smem_u32(smem);
    const int wid  = tid >> 5;
    const int lane = tid & 31;

    uint32_t t_sw[4];
    const __nv_bfloat16* a_src[4];
    const __nv_bfloat16* b_src[4];
#pragma unroll
    for (int i = 0; i < 4; i++) {
        int idx = i * 256 + tid, row = idx >> 3, c = idx & 7;
        t_sw[i] = SW128(row * 128 + c * 16);
        a_src[i] = g_A2 + (size_t)(bm + row) * 512 + c * 8;
        b_src[i] = g_B2 + (size_t)(bn + row) * 512 + c * 8;
    }

    const int wm0 = (wid >> 1) * 32;
    const int wn0 = (wid & 1) * 64;
    const int a_row  = wm0 + (lane & 7) + ((lane & 8) ? 8 : 0);
    const int a_koff = (lane & 16) ? 16 : 0;
    const int b_row  = wn0 + (lane & 7) + ((lane & 16) ? 8 : 0);
    const int b_koff = (lane & 8) ? 16 : 0;

    float acc[2][8][4];
#pragma unroll
    for (int mt = 0; mt < 2; mt++)
#pragma unroll
        for (int nt = 0; nt < 8; nt++)
#pragma unroll
            for (int q = 0; q < 4; q++) acc[mt][nt][q] = 0.f;

    auto prefetch = [&](int ch) {
        const int seg = ch >> 2, s = ch & 3;
        const int aoff = ((seg == 1) ? 256 : 0) + s * 64;
        const int boff = ((seg == 2) ? 256 : 0) + s * 64;
        const uint32_t base = sb + (ch % NSTAGE) * STAGE_BYTES;
#pragma unroll
        for (int i = 0; i < 4; i++) cp_async16(base + t_sw[i], a_src[i] + aoff);
#pragma unroll
        for (int i = 0; i < 4; i++) cp_async16(base + TILE_BYTES + t_sw[i], b_src[i] + boff);
        asm volatile("cp.async.commit_group;" ::: "memory");
    };

    prefetch(0);
    prefetch(1);

#pragma unroll 1
    for (int ch = 0; ch < 12; ++ch) {
        if (ch < 11) asm volatile("cp.async.wait_group 1;" ::: "memory");
        else         asm volatile("cp.async.wait_group 0;" ::: "memory");
        __syncthreads();
        if (ch + 2 < 12) prefetch(ch + 2);

        const uint32_t Ab = sb + (ch % NSTAGE) * STAGE_BYTES;
        const uint32_t Bb = Ab + TILE_BYTES;

#pragma unroll
        for (int ks = 0; ks < 4; ++ks) {
            const int kb = ks * 32;
            uint32_t a[2][4], b[4][4];
#pragma unroll
            for (int mt = 0; mt < 2; mt++)
                ldsm4(a[mt], Ab + SW128((a_row + mt * 16) * 128 + kb + a_koff));
#pragma unroll
            for (int p = 0; p < 4; p++)
                ldsm4(b[p], Bb + SW128((b_row + p * 16) * 128 + kb + b_koff));
#pragma unroll
            for (int mt = 0; mt < 2; mt++)
#pragma unroll
                for (int p = 0; p < 4; p++) {
                    mma16816(acc[mt][2 * p + 0], a[mt], b[p][0], b[p][1]);
                    mma16816(acc[mt][2 * p + 1], a[mt], b[p][2], b[p][3]);
                }
        }
    }

    // epilogue: C row for tile-local row b is m_orig = b*SS + tT
    const int lm = lane >> 2;
    const int lq = (lane & 3) * 2;
#pragma unroll
    for (int nt = 0; nt < 8; nt++) {
        const int gcol = bn + wn0 + nt * 8 + lq;
        if (gcol >= VV) continue;
        const float2 bv = *(const float2*)(ba + gcol);
#pragma unroll
        for (int mt = 0; mt < 2; mt++) {
            const int brow = wm0 + mt * 16 + lm;             // batch index
            float* c0 = C + ((size_t)brow * SS + tT) * VV + gcol;
            float2 o0 = make_float2(acc[mt][nt][0] + bv.x, acc[mt][nt][1] + bv.y);
            float2 o1 = make_float2(acc[mt][nt][2] + bv.x, acc[mt][nt][3] + bv.y);
            *(float2*)c0                         = o0;
            *(float2*)(c0 + (size_t)8 * SS * VV) = o1;       // brow+8
        }
    }
}

// ============================================================================
extern "C" void kernel_launch(void* const* d_in, const int* in_sizes, int n_in,
                              void* d_out, int out_size)
{
    const int*   x     = (const int*)  d_in[0];
    const float* emb   = (const float*)d_in[1];
    const float* W_ih  = (const float*)d_in[2];
    const float* W_hh  = (const float*)d_in[3];
    const float* b_ih  = (const float*)d_in[4];
    const float* b_hh  = (const float*)d_in[5];
    const float* W_aff = (const float*)d_in[6];
    const float* b_aff = (const float*)d_in[7];
    float* out = (float*)d_out;

    cudaFuncSetAttribute(fused_rnn_gemm, cudaFuncAttributeMaxDynamicSharedMemorySize, SMEM_FUSED);

    prep<<<NB_PREP, 256>>>(x, emb, W_ih, b_ih, b_hh, W_hh, W_aff);
    fused_rnn_gemm<<<NB_FUSED, 256, SMEM_FUSED>>>(b_aff, out);
}

// round 11
// speedup vs baseline: 1.0728x; 1.0728x over previous
#include <cuda_runtime.h>
#include <cuda_bf16.h>
#include <cstdint>

#define BB 128
#define SS 50
#define XX 128
#define HH 256
#define VV 10000
#define MM (BB*SS)     // 6400
#define NT_N 79
#define NPAD (NT_N * 128)   // 10112
#define N_TICKETS (SS * NT_N)

// ---------------- device scratch (no allocs allowed in kernel_launch) ------
__device__ float g_xin[MM * HH];                         // input projection [b][t][j]
__device__ float g_WT[HH * HH];                          // W_hh transposed: [k][j]
// t-MAJOR: row m = t*128 + b ; [m][0:256]=hi, [256:512]=lo
__device__ __align__(16) __nv_bfloat16 g_A2[MM * 512];
__device__ __align__(16) __nv_bfloat16 g_B2[(size_t)NPAD * 512]; // split of W_aff
__device__ int g_prog[SS];                               // per-step producer arrivals
__device__ int g_ticket;                                 // persistent consumer tickets

// ---------------- packed fp32x2 helpers --------------------------------------
__device__ __forceinline__ double dup2(float x) {
    double r; asm("mov.b64 %0, {%1, %1};" : "=d"(r) : "f"(x)); return r;
}
__device__ __forceinline__ double pk2(float lo, float hi) {
    double r; asm("mov.b64 %0, {%1, %2};" : "=d"(r) : "f"(lo), "f"(hi)); return r;
}
__device__ __forceinline__ float2 unpk(double d) {
    float2 f; asm("mov.b64 {%0, %1}, %2;" : "=f"(f.x), "=f"(f.y) : "d"(d)); return f;
}
__device__ __forceinline__ void ffma2(double& acc, double a, double b) {
    asm("fma.rn.f32x2 %0, %1, %2, %0;" : "+d"(acc) : "d"(a), "d"(b));
}
__device__ __forceinline__ double fadd2(double a, double b) {
    double r; asm("add.rn.f32x2 %0, %1, %2;" : "=d"(r) : "d"(a), "d"(b)); return r;
}

// ---------------- mma / smem helpers ------------------------------------------
__device__ __forceinline__ uint32_t smem_u32(const void* p) {
    uint32_t a;
    asm("{ .reg .u64 t; cvta.to.shared.u64 t, %1; cvt.u32.u64 %0, t; }" : "=r"(a) : "l"(p));
    return a;
}
__device__ __forceinline__ void cp_async16(uint32_t dst, const void* src) {
    asm volatile("cp.async.cg.shared.global [%0], [%1], 16;"
                 :: "r"(dst), "l"(src) : "memory");
}
__device__ __forceinline__ void ldsm4(uint32_t r[4], uint32_t addr) {
    asm volatile("ldmatrix.sync.aligned.m8n8.x4.shared.b16 {%0,%1,%2,%3}, [%4];"
                 : "=r"(r[0]), "=r"(r[1]), "=r"(r[2]), "=r"(r[3]) : "r"(addr));
}
__device__ __forceinline__ void mma16816(float c[4], const uint32_t a[4],
                                         uint32_t b0, uint32_t b1) {
    asm volatile(
        "mma.sync.aligned.m16n8k16.row.col.f32.bf16.bf16.f32 "
        "{%0,%1,%2,%3}, {%4,%5,%6,%7}, {%8,%9}, {%0,%1,%2,%3};"
        : "+f"(c[0]), "+f"(c[1]), "+f"(c[2]), "+f"(c[3])
        : "r"(a[0]), "r"(a[1]), "r"(a[2]), "r"(a[3]), "r"(b0), "r"(b1));
}
__device__ __forceinline__ int ld_acq(const int* p) {
    int v; asm volatile("ld.acquire.gpu.global.b32 %0, [%1];" : "=r"(v) : "l"(p)); return v;
}
__device__ __forceinline__ void red_release(int* p) {
    asm volatile("red.release.gpu.global.add.s32 [%0], %1;" :: "l"(p), "r"(1) : "memory");
}
#define SW128(x) ((x) ^ (((x) >> 3) & 0x70))

__device__ __forceinline__ void store_split(__nv_bfloat16* p, float v) {
    __nv_bfloat16 hi = __float2bfloat16(v);
    p[0]   = hi;
    p[256] = __float2bfloat16(v - __bfloat162float(hi));
}

// ============================================================================
// Kernel A (fused prep): embed+proj | split W_aff | transpose W_hh | reset sync
// ============================================================================
#define NB_EMB 400
#define NB_SPL (NPAD / 4)        // 2528
#define NB_TRA 256
#define NB_PREP (NB_EMB + NB_SPL + NB_TRA)

__global__ void __launch_bounds__(256)
prep(const int* __restrict__ xraw,
     const float* __restrict__ emb,
     const float* __restrict__ W_ih,
     const float* __restrict__ b_ih,
     const float* __restrict__ b_hh,
     const float* __restrict__ W_hh,
     const float* __restrict__ Wa)
{
    const int bb = blockIdx.x;

    if (bb >= NB_EMB + NB_SPL) {                 // ---- transpose W_hh ----
        int idx = (bb - NB_EMB - NB_SPL) * 256 + threadIdx.x;  // 65536 elems
        int k = idx >> 8, j = idx & 255;
        g_WT[k * HH + j] = W_hh[j * HH + k];
        return;
    }
    if (bb >= NB_EMB) {                          // ---- split W_aff ----
        int idx = (bb - NB_EMB) * 256 + threadIdx.x;   // NPAD * 64
        int n  = idx >> 6;
        int k4 = (idx & 63) << 2;
        float4 w = make_float4(0.f, 0.f, 0.f, 0.f);
        if (n < VV) w = *(const float4*)(Wa + (size_t)n * 256 + k4);
        __nv_bfloat16* p = g_B2 + (size_t)n * 512 + k4;
        __nv_bfloat16 h0 = __float2bfloat16(w.x);
        __nv_bfloat16 h1 = __float2bfloat16(w.y);
        __nv_bfloat16 h2 = __float2bfloat16(w.z);
        __nv_bfloat16 h3 = __float2bfloat16(w.w);
        p[0] = h0; p[1] = h1; p[2] = h2; p[3] = h3;
        p[256] = __float2bfloat16(w.x - __bfloat162float(h0));
        p[257] = __float2bfloat16(w.y - __bfloat162float(h1));
        p[258] = __float2bfloat16(w.z - __bfloat162float(h2));
        p[259] = __float2bfloat16(w.w - __bfloat162float(h3));
        return;
    }

    // ---- embedding + input projection (16 rows per block) ----
    if (bb == 0 && threadIdx.x < SS) g_prog[threadIdx.x] = 0;   // reset progress
    if (bb == 0 && threadIdx.x == 255) g_ticket = 0;            // reset tickets

    __shared__ __align__(16) float se[16][XX];

    const bool is64 = ((xraw[1] | xraw[3] | xraw[5] | xraw[7] | xraw[9]) == 0) &&
                      ((xraw[0] | xraw[2] | xraw[4] | xraw[6] | xraw[8]) != 0);

    const int m0 = bb * 16;
    for (int i = threadIdx.x; i < 16 * (XX / 4); i += 256) {
        int r = i >> 5, c = i & 31;
        int m = m0 + r;
        int tok = is64 ? xraw[2 * m] : xraw[m];
        ((float4*)se[r])[c] = ((const float4*)(emb + (long long)tok * XX))[c];
    }
    __syncthreads();

    const int j = threadIdx.x;
    const float bias = b_ih[j] + b_hh[j];
    float acc[16];
#pragma unroll
    for (int r = 0; r < 16; r++) acc[r] = bias;

    const float* wr = W_ih + j * XX;
#pragma unroll 4
    for (int k = 0; k < XX; k += 4) {
        float4 w = *(const float4*)(wr + k);
#pragma unroll
        for (int r = 0; r < 16; r++) {
            float4 e = *(const float4*)&se[r][k];
            acc[r] = fmaf(w.x, e.x, fmaf(w.y, e.y, fmaf(w.z, e.z, fmaf(w.w, e.w, acc[r]))));
        }
    }
#pragma unroll
    for (int r = 0; r < 16; r++)
        g_xin[(m0 + r) * HH + j] = acc[r];
}

// ============================================================================
// Persistent GEMM consumer loop (shared by both kernels).
//   Ticket k -> tile (t = k/NT_N, n-tile = k%NT_N); waits g_prog[t] == 64.
// ============================================================================
#define RNN_W_F2   (128 * 64)            // float2: quarter of W
#define RNN_HB_F2  (2 * 4 * 256)         // [buf][rq][col]
#define TILE_BYTES 16384
#define STAGE_BYTES (2 * TILE_BYTES)
#define NSTAGE 3
#define SMEM_TILES (NSTAGE * STAGE_BYTES)   // 98304 (rnn scan uses 80 KB subset)
#define NB_RNN 64
#define NB_GEMM 232

__device__ void consume_tiles(const float* __restrict__ ba, float* __restrict__ C,
                              char* smem, int tid)
{
    const uint32_t sb = smem_u32(smem);
    const int wid  = tid >> 5;
    const int lane = tid & 31;

    uint32_t t_sw[4];
    int l_row[4], l_c[4];
#pragma unroll
    for (int i = 0; i < 4; i++) {
        int idx = i * 256 + tid;
        l_row[i] = idx >> 3; l_c[i] = idx & 7;
        t_sw[i] = SW128(l_row[i] * 128 + l_c[i] * 16);
    }

    const int wm0 = (wid >> 1) * 32;
    const int wn0 = (wid & 1) * 64;
    const int a_row  = wm0 + (lane & 7) + ((lane & 8) ? 8 : 0);
    const int a_koff = (lane & 16) ? 16 : 0;
    const int b_row  = wn0 + (lane & 7) + ((lane & 16) ? 8 : 0);
    const int b_koff = (lane & 8) ? 16 : 0;
    const int lm = lane >> 2;
    const int lq = (lane & 3) * 2;

    __shared__ int s_ticket;

    for (;;) {
        if (tid == 0) s_ticket = atomicAdd(&g_ticket, 1);
        __syncthreads();
        const int ticket = s_ticket;
        __syncthreads();
        if (ticket >= N_TICKETS) return;

        const int tT = ticket / NT_N;
        const int bn = (ticket % NT_N) * 128;
        const int bm = tT * 128;

        if (tid == 0) {
            while (ld_acq(&g_prog[tT]) < NB_RNN) __nanosleep(128);
        }
        __syncthreads();

        const __nv_bfloat16* a_src[4];
        const __nv_bfloat16* b_src[4];
#pragma unroll
        for (int i = 0; i < 4; i++) {
            a_src[i] = g_A2 + (size_t)(bm + l_row[i]) * 512 + l_c[i] * 8;
            b_src[i] = g_B2 + (size_t)(bn + l_row[i]) * 512 + l_c[i] * 8;
        }

        float acc[2][8][4];
#pragma unroll
        for (int mt = 0; mt < 2; mt++)
#pragma unroll
            for (int nt = 0; nt < 8; nt++)
#pragma unroll
                for (int q = 0; q < 4; q++) acc[mt][nt][q] = 0.f;

        auto prefetch = [&](int ch) {
            const int seg = ch >> 2, s = ch & 3;
            const int aoff = ((seg == 1) ? 256 : 0) + s * 64;
            const int boff = ((seg == 2) ? 256 : 0) + s * 64;
            const uint32_t base = sb + (ch % NSTAGE) * STAGE_BYTES;
#pragma unroll
            for (int i = 0; i < 4; i++) cp_async16(base + t_sw[i], a_src[i] + aoff);
#pragma unroll
            for (int i = 0; i < 4; i++) cp_async16(base + TILE_BYTES + t_sw[i], b_src[i] + boff);
            asm volatile("cp.async.commit_group;" ::: "memory");
        };

        prefetch(0);
        prefetch(1);

#pragma unroll 1
        for (int ch = 0; ch < 12; ++ch) {
            if (ch < 11) asm volatile("cp.async.wait_group 1;" ::: "memory");
            else         asm volatile("cp.async.wait_group 0;" ::: "memory");
            __syncthreads();
            if (ch + 2 < 12) prefetch(ch + 2);

            const uint32_t Ab = sb + (ch % NSTAGE) * STAGE_BYTES;
            const uint32_t Bb = Ab + TILE_BYTES;

#pragma unroll
            for (int ks = 0; ks < 4; ++ks) {
                const int kb = ks * 32;
                uint32_t a[2][4], b[4][4];
#pragma unroll
                for (int mt = 0; mt < 2; mt++)
                    ldsm4(a[mt], Ab + SW128((a_row + mt * 16) * 128 + kb + a_koff));
#pragma unroll
                for (int p = 0; p < 4; p++)
                    ldsm4(b[p], Bb + SW128((b_row + p * 16) * 128 + kb + b_koff));
#pragma unroll
                for (int mt = 0; mt < 2; mt++)
#pragma unroll
                    for (int p = 0; p < 4; p++) {
                        mma16816(acc[mt][2 * p + 0], a[mt], b[p][0], b[p][1]);
                        mma16816(acc[mt][2 * p + 1], a[mt], b[p][2], b[p][3]);
                    }
            }
        }

        // epilogue: C row for tile-local row b is m_orig = b*SS + tT
#pragma unroll
        for (int nt = 0; nt < 8; nt++) {
            const int gcol = bn + wn0 + nt * 8 + lq;
            if (gcol >= VV) continue;
            const float2 bv = *(const float2*)(ba + gcol);
#pragma unroll
            for (int mt = 0; mt < 2; mt++) {
                const int brow = wm0 + mt * 16 + lm;             // batch index
                float* c0 = C + ((size_t)brow * SS + tT) * VV + gcol;
                float2 o0 = make_float2(acc[mt][nt][0] + bv.x, acc[mt][nt][1] + bv.y);
                float2 o1 = make_float2(acc[mt][nt][2] + bv.x, acc[mt][nt][3] + bv.y);
                *(float2*)c0                         = o0;
                *(float2*)(c0 + (size_t)8 * SS * VV) = o1;       // brow+8
            }
        }
        __syncthreads();
    }
}

// ============================================================================
// RNN kernel (cluster-4, 64 CTAs). After the scan, CTAs become gemm consumers.
// ============================================================================
__global__ void __launch_bounds__(256, 2) __cluster_dims__(4, 1, 1)
rnn_then_consume(const float* __restrict__ ba, float* __restrict__ C)
{
    extern __shared__ __align__(1024) char smem[];
    const int bid = blockIdx.x;
    const int tid = threadIdx.x;

    {
        float2* wsp = (float2*)smem;            // [k2*64 + jl], k2=0..127
        float2* hb  = (float2*)smem + RNN_W_F2; // [(buf*4 + rq)*256 + col]
        const uint32_t hb_addr = smem_u32(hb);

        const int rq   = tid >> 6;              // rowpair 0..3
        const int jl   = tid & 63;
        const uint32_t rank = bid & 3;
        const int jg   = rank * 64 + jl;        // global output column
        const int b0   = (bid >> 2) * 8;        // 8 batch rows per cluster

        for (int i = tid; i < RNN_W_F2; i += 256) {
            int k2 = i >> 6, j = i & 63;
            int jgl = rank * 64 + j;
            wsp[i] = make_float2(g_WT[(2 * k2) * HH + jgl],
                                 g_WT[(2 * k2 + 1) * HH + jgl]);
        }
        for (int i = tid; i < 4 * 256; i += 256) hb[i] = make_float2(0.f, 0.f);

        asm volatile("barrier.cluster.arrive.aligned;" ::: "memory");
        asm volatile("barrier.cluster.wait.aligned;" ::: "memory");

        const int r0 = b0 + 2 * rq;
        const float* x0p = g_xin + (size_t)r0 * SS * HH + jg;
        const float* x1p = g_xin + (size_t)(r0 + 1) * SS * HH + jg;
        __nv_bfloat16* a0p = g_A2 + (size_t)r0 * 512 + jg;        // + t*BB*512
        __nv_bfloat16* a1p = g_A2 + (size_t)(r0 + 1) * 512 + jg;

        const float2* wp = wsp + jl;
        const uint32_t p1 = rank ^ 1, p2 = rank ^ 2, p3 = rank ^ 3;

        float xa = x0p[0], xb = x1p[0];
        int cur = 0;
        for (int t = 0; t < SS; ++t) {
            double acc_e = pk2(xa, xb);
            double acc_o = 0.0;
            if (t + 1 < SS) {
                xa = x0p[(size_t)(t + 1) * HH];
                xb = x1p[(size_t)(t + 1) * HH];
            }

            const double2* hc = (const double2*)(hb + (cur * 4 + rq) * 256);
#pragma unroll 8
            for (int k2 = 0; k2 < 128; ++k2) {
                float2 wv  = wp[k2 * 64];
                double2 h2 = hc[k2];
                ffma2(acc_e, dup2(wv.x), h2.x);
                ffma2(acc_o, dup2(wv.y), h2.y);
            }

            float2 f = unpk(fadd2(acc_e, acc_o));
            float h0 = tanhf(f.x), h1 = tanhf(f.y);

            const int nxt = cur ^ 1;
            const long long hp = __double_as_longlong(pk2(h0, h1));
            uint32_t loc = hb_addr + (uint32_t)(((nxt * 4 + rq) * 256 + jg) * 8);
            asm volatile("st.shared.b64 [%0], %1;" :: "r"(loc), "l"(hp) : "memory");
            asm volatile(
                "{\n\t.reg .b32 ra;\n\t"
                "mapa.shared::cluster.u32 ra, %0, %1;\n\t"
                "st.shared::cluster.b64 [ra], %2;\n\t"
                "mapa.shared::cluster.u32 ra, %0, %3;\n\t"
                "st.shared::cluster.b64 [ra], %2;\n\t"
                "mapa.shared::cluster.u32 ra, %0, %4;\n\t"
                "st.shared::cluster.b64 [ra], %2;\n\t}"
                :: "r"(loc), "r"(p1), "l"(hp), "r"(p2), "r"(p3) : "memory");

            store_split(a0p + (size_t)t * (BB * 512), h0);
            store_split(a1p + (size_t)t * (BB * 512), h1);

            asm volatile("barrier.cluster.arrive.aligned;" ::: "memory");
            asm volatile("barrier.cluster.wait.aligned;" ::: "memory");
            if (tid == 0) red_release(&g_prog[t]);
            cur = nxt;
        }
    }
    __syncthreads();
    // Scan done: convert this CTA into a gemm consumer (reuses smem).
    consume_tiles(ba, C, smem, tid);
}

// ============================================================================
// Pure consumer kernel (no cluster -> full scheduling flexibility)
// ============================================================================
__global__ void __launch_bounds__(256, 2)
gemm_consume(const float* __restrict__ ba, float* __restrict__ C)
{
    extern __shared__ __align__(1024) char smem[];
    consume_tiles(ba, C, smem, threadIdx.x);
}

// ============================================================================
extern "C" void kernel_launch(void* const* d_in, const int* in_sizes, int n_in,
                              void* d_out, int out_size)
{
    const int*   x     = (const int*)  d_in[0];
    const float* emb   = (const float*)d_in[1];
    const float* W_ih  = (const float*)d_in[2];
    const float* W_hh  = (const float*)d_in[3];
    const float* b_ih  = (const float*)d_in[4];
    const float* b_hh  = (const float*)d_in[5];
    const float* W_aff = (const float*)d_in[6];
    const float* b_aff = (const float*)d_in[7];
    float* out = (float*)d_out;

    static cudaStream_t s2 = nullptr;
    static cudaEvent_t evA = nullptr, evB = nullptr;
    if (s2 == nullptr) {
        cudaStreamCreateWithFlags(&s2, cudaStreamNonBlocking);
        cudaEventCreateWithFlags(&evA, cudaEventDisableTiming);
        cudaEventCreateWithFlags(&evB, cudaEventDisableTiming);
        cudaFuncSetAttribute(rnn_then_consume,
                             cudaFuncAttributeMaxDynamicSharedMemorySize, SMEM_TILES);
        cudaFuncSetAttribute(gemm_consume,
                             cudaFuncAttributeMaxDynamicSharedMemorySize, SMEM_TILES);
    }

    prep<<<NB_PREP, 256>>>(x, emb, W_ih, b_ih, b_hh, W_hh, W_aff);

    // fork: consumers run concurrently with the rnn producer kernel
    cudaEventRecord(evA, 0);
    cudaStreamWaitEvent(s2, evA, 0);

    rnn_then_consume<<<NB_RNN, 256, SMEM_TILES>>>(b_aff, out);          // stream 0
    gemm_consume<<<NB_GEMM, 256, SMEM_TILES, s2>>>(b_aff, out);         // stream s2

    // join
    cudaEventRecord(evB, s2);
    cudaStreamWaitEvent(0, evB, 0);
}

// round 12
// speedup vs baseline: 1.3085x; 1.2197x over previous
#include <cuda_runtime.h>
#include <cuda_fp16.h>
#include <cstdint>

#define BB 128
#define SS 50
#define XX 128
#define HH 256
#define VV 10000
#define MM (BB*SS)     // 6400
#define NT_N 79
#define NPAD (NT_N * 128)   // 10112
#define N_TICKETS (SS * NT_N)

// ---------------- device scratch (no allocs allowed in kernel_launch) ------
__device__ float g_xin[MM * HH];                         // input projection [b][t][j]
__device__ float g_WT[HH * HH];                          // W_hh transposed: [k][j]
// t-MAJOR: row m = t*128 + b ; [m][0:256]=hi, [256:512]=lo  (fp16 split of h)
__device__ __align__(16) __half g_A2[MM * 512];
__device__ __align__(16) __half g_B2[(size_t)NPAD * 256];   // W_aff in plain fp16
__device__ int g_prog[SS];                               // per-step producer arrivals
__device__ int g_ticket;                                 // persistent consumer tickets

// ---------------- packed fp32x2 helpers --------------------------------------
__device__ __forceinline__ double dup2(float x) {
    double r; asm("mov.b64 %0, {%1, %1};" : "=d"(r) : "f"(x)); return r;
}
__device__ __forceinline__ double pk2(float lo, float hi) {
    double r; asm("mov.b64 %0, {%1, %2};" : "=d"(r) : "f"(lo), "f"(hi)); return r;
}
__device__ __forceinline__ float2 unpk(double d) {
    float2 f; asm("mov.b64 {%0, %1}, %2;" : "=f"(f.x), "=f"(f.y) : "d"(d)); return f;
}
__device__ __forceinline__ void ffma2(double& acc, double a, double b) {
    asm("fma.rn.f32x2 %0, %1, %2, %0;" : "+d"(acc) : "d"(a), "d"(b));
}
__device__ __forceinline__ double fadd2(double a, double b) {
    double r; asm("add.rn.f32x2 %0, %1, %2;" : "=d"(r) : "d"(a), "d"(b)); return r;
}

// ---------------- mma / smem helpers ------------------------------------------
__device__ __forceinline__ uint32_t smem_u32(const void* p) {
    uint32_t a;
    asm("{ .reg .u64 t; cvta.to.shared.u64 t, %1; cvt.u32.u64 %0, t; }" : "=r"(a) : "l"(p));
    return a;
}
__device__ __forceinline__ void cp_async16(uint32_t dst, const void* src) {
    asm volatile("cp.async.cg.shared.global [%0], [%1], 16;"
                 :: "r"(dst), "l"(src) : "memory");
}
__device__ __forceinline__ void ldsm4(uint32_t r[4], uint32_t addr) {
    asm volatile("ldmatrix.sync.aligned.m8n8.x4.shared.b16 {%0,%1,%2,%3}, [%4];"
                 : "=r"(r[0]), "=r"(r[1]), "=r"(r[2]), "=r"(r[3]) : "r"(addr));
}
__device__ __forceinline__ void mma16816(float c[4], const uint32_t a[4],
                                         uint32_t b0, uint32_t b1) {
    asm volatile(
        "mma.sync.aligned.m16n8k16.row.col.f32.f16.f16.f32 "
        "{%0,%1,%2,%3}, {%4,%5,%6,%7}, {%8,%9}, {%0,%1,%2,%3};"
        : "+f"(c[0]), "+f"(c[1]), "+f"(c[2]), "+f"(c[3])
        : "r"(a[0]), "r"(a[1]), "r"(a[2]), "r"(a[3]), "r"(b0), "r"(b1));
}
__device__ __forceinline__ int ld_acq(const int* p) {
    int v; asm volatile("ld.acquire.gpu.global.b32 %0, [%1];" : "=r"(v) : "l"(p)); return v;
}
__device__ __forceinline__ void red_release(int* p) {
    asm volatile("red.release.gpu.global.add.s32 [%0], %1;" :: "l"(p), "r"(1) : "memory");
}
#define SW128(x) ((x) ^ (((x) >> 3) & 0x70))

__device__ __forceinline__ void store_split(__half* p, float v) {
    __half hi = __float2half_rn(v);
    p[0]   = hi;
    p[256] = __float2half_rn(v - __half2float(hi));
}

// ============================================================================
// Kernel A (fused prep): embed+proj | fp16 W_aff | transpose W_hh | reset sync
// ============================================================================
#define NB_EMB 400
#define NB_SPL (NPAD / 4)        // 2528
#define NB_TRA 256
#define NB_PREP (NB_EMB + NB_SPL + NB_TRA)

__global__ void __launch_bounds__(256)
prep(const int* __restrict__ xraw,
     const float* __restrict__ emb,
     const float* __restrict__ W_ih,
     const float* __restrict__ b_ih,
     const float* __restrict__ b_hh,
     const float* __restrict__ W_hh,
     const float* __restrict__ Wa)
{
    const int bb = blockIdx.x;

    if (bb >= NB_EMB + NB_SPL) {                 // ---- transpose W_hh ----
        int idx = (bb - NB_EMB - NB_SPL) * 256 + threadIdx.x;  // 65536 elems
        int k = idx >> 8, j = idx & 255;
        g_WT[k * HH + j] = W_hh[j * HH + k];
        return;
    }
    if (bb >= NB_EMB) {                          // ---- W_aff -> fp16 ----
        int idx = (bb - NB_EMB) * 256 + threadIdx.x;   // NPAD * 64
        int n  = idx >> 6;
        int k4 = (idx & 63) << 2;
        float4 w = make_float4(0.f, 0.f, 0.f, 0.f);
        if (n < VV) w = *(const float4*)(Wa + (size_t)n * 256 + k4);
        __half* p = g_B2 + (size_t)n * 256 + k4;
        p[0] = __float2half_rn(w.x);
        p[1] = __float2half_rn(w.y);
        p[2] = __float2half_rn(w.z);
        p[3] = __float2half_rn(w.w);
        return;
    }

    // ---- embedding + input projection (16 rows per block) ----
    if (bb == 0 && threadIdx.x < SS) g_prog[threadIdx.x] = 0;   // reset progress
    if (bb == 0 && threadIdx.x == 255) g_ticket = 0;            // reset tickets

    __shared__ __align__(16) float se[16][XX];

    const bool is64 = ((xraw[1] | xraw[3] | xraw[5] | xraw[7] | xraw[9]) == 0) &&
                      ((xraw[0] | xraw[2] | xraw[4] | xraw[6] | xraw[8]) != 0);

    const int m0 = bb * 16;
    for (int i = threadIdx.x; i < 16 * (XX / 4); i += 256) {
        int r = i >> 5, c = i & 31;
        int m = m0 + r;
        int tok = is64 ? xraw[2 * m] : xraw[m];
        ((float4*)se[r])[c] = ((const float4*)(emb + (long long)tok * XX))[c];
    }
    __syncthreads();

    const int j = threadIdx.x;
    const float bias = b_ih[j] + b_hh[j];
    float acc[16];
#pragma unroll
    for (int r = 0; r < 16; r++) acc[r] = bias;

    const float* wr = W_ih + j * XX;
#pragma unroll 4
    for (int k = 0; k < XX; k += 4) {
        float4 w = *(const float4*)(wr + k);
#pragma unroll
        for (int r = 0; r < 16; r++) {
            float4 e = *(const float4*)&se[r][k];
            acc[r] = fmaf(w.x, e.x, fmaf(w.y, e.y, fmaf(w.z, e.z, fmaf(w.w, e.w, acc[r]))));
        }
    }
#pragma unroll
    for (int r = 0; r < 16; r++)
        g_xin[(m0 + r) * HH + j] = acc[r];
}

// ============================================================================
// Persistent GEMM consumer loop.
//   C[m][n] = A_hi.B + A_lo.B + bias   (fp16 x fp16 -> fp32, K_eff = 512)
//   Ticket k -> tile (t = k/NT_N, n-tile = k%NT_N); waits g_prog[t] == 64.
// ============================================================================
#define RNN_W_F2   (128 * 64)            // float2: quarter of W
#define RNN_HB_F2  (2 * 4 * 256)         // [buf][rq][col]
#define TILE_BYTES 16384
#define STAGE_BYTES (2 * TILE_BYTES)
#define NSTAGE 3
#define SMEM_TILES (NSTAGE * STAGE_BYTES)   // 98304 (rnn scan uses 80 KB subset)
#define NB_RNN 64
#define NB_GEMM 232
#define NCHUNK 8

__device__ void consume_tiles(const float* __restrict__ ba, float* __restrict__ C,
                              char* smem, int tid)
{
    const uint32_t sb = smem_u32(smem);
    const int wid  = tid >> 5;
    const int lane = tid & 31;

    uint32_t t_sw[4];
    int l_row[4], l_c[4];
#pragma unroll
    for (int i = 0; i < 4; i++) {
        int idx = i * 256 + tid;
        l_row[i] = idx >> 3; l_c[i] = idx & 7;
        t_sw[i] = SW128(l_row[i] * 128 + l_c[i] * 16);
    }

    const int wm0 = (wid >> 1) * 32;
    const int wn0 = (wid & 1) * 64;
    const int a_row  = wm0 + (lane & 7) + ((lane & 8) ? 8 : 0);
    const int a_koff = (lane & 16) ? 16 : 0;
    const int b_row  = wn0 + (lane & 7) + ((lane & 16) ? 8 : 0);
    const int b_koff = (lane & 8) ? 16 : 0;
    const int lm = lane >> 2;
    const int lq = (lane & 3) * 2;

    __shared__ int s_ticket;

    for (;;) {
        if (tid == 0) s_ticket = atomicAdd(&g_ticket, 1);
        __syncthreads();
        const int ticket = s_ticket;
        __syncthreads();
        if (ticket >= N_TICKETS) return;

        const int tT = ticket / NT_N;
        const int bn = (ticket % NT_N) * 128;
        const int bm = tT * 128;

        if (tid == 0) {
            while (ld_acq(&g_prog[tT]) < NB_RNN) __nanosleep(128);
        }
        __syncthreads();

        const __half* a_src[4];
        const __half* b_src[4];
#pragma unroll
        for (int i = 0; i < 4; i++) {
            a_src[i] = g_A2 + (size_t)(bm + l_row[i]) * 512 + l_c[i] * 8;
            b_src[i] = g_B2 + (size_t)(bn + l_row[i]) * 256 + l_c[i] * 8;
        }

        float acc[2][8][4];
#pragma unroll
        for (int mt = 0; mt < 2; mt++)
#pragma unroll
            for (int nt = 0; nt < 8; nt++)
#pragma unroll
                for (int q = 0; q < 4; q++) acc[mt][nt][q] = 0.f;

        // chunks: seg = ch>>2 (0: A_hi, 1: A_lo), s = ch&3 (k quarter)
        auto prefetch = [&](int ch) {
            const int seg = ch >> 2, s = ch & 3;
            const int aoff = seg * 256 + s * 64;
            const int boff = s * 64;
            const uint32_t base = sb + (ch % NSTAGE) * STAGE_BYTES;
#pragma unroll
            for (int i = 0; i < 4; i++) cp_async16(base + t_sw[i], a_src[i] + aoff);
#pragma unroll
            for (int i = 0; i < 4; i++) cp_async16(base + TILE_BYTES + t_sw[i], b_src[i] + boff);
            asm volatile("cp.async.commit_group;" ::: "memory");
        };

        prefetch(0);
        prefetch(1);

#pragma unroll 1
        for (int ch = 0; ch < NCHUNK; ++ch) {
            if (ch < NCHUNK - 1) asm volatile("cp.async.wait_group 1;" ::: "memory");
            else                 asm volatile("cp.async.wait_group 0;" ::: "memory");
            __syncthreads();
            if (ch + 2 < NCHUNK) prefetch(ch + 2);

            const uint32_t Ab = sb + (ch % NSTAGE) * STAGE_BYTES;
            const uint32_t Bb = Ab + TILE_BYTES;

#pragma unroll
            for (int ks = 0; ks < 4; ++ks) {
                const int kb = ks * 32;
                uint32_t a[2][4], b[4][4];
#pragma unroll
                for (int mt = 0; mt < 2; mt++)
                    ldsm4(a[mt], Ab + SW128((a_row + mt * 16) * 128 + kb + a_koff));
#pragma unroll
                for (int p = 0; p < 4; p++)
                    ldsm4(b[p], Bb + SW128((b_row + p * 16) * 128 + kb + b_koff));
#pragma unroll
                for (int mt = 0; mt < 2; mt++)
#pragma unroll
                    for (int p = 0; p < 4; p++) {
                        mma16816(acc[mt][2 * p + 0], a[mt], b[p][0], b[p][1]);
                        mma16816(acc[mt][2 * p + 1], a[mt], b[p][2], b[p][3]);
                    }
            }
        }

        // epilogue: C row for tile-local row b is m_orig = b*SS + tT
#pragma unroll
        for (int nt = 0; nt < 8; nt++) {
            const int gcol = bn + wn0 + nt * 8 + lq;
            if (gcol >= VV) continue;
            const float2 bv = *(const float2*)(ba + gcol);
#pragma unroll
            for (int mt = 0; mt < 2; mt++) {
                const int brow = wm0 + mt * 16 + lm;             // batch index
                float* c0 = C + ((size_t)brow * SS + tT) * VV + gcol;
                float2 o0 = make_float2(acc[mt][nt][0] + bv.x, acc[mt][nt][1] + bv.y);
                float2 o1 = make_float2(acc[mt][nt][2] + bv.x, acc[mt][nt][3] + bv.y);
                *(float2*)c0                         = o0;
                *(float2*)(c0 + (size_t)8 * SS * VV) = o1;       // brow+8
            }
        }
        __syncthreads();
    }
}

// ============================================================================
// RNN kernel (cluster-4, 64 CTAs). After the scan, CTAs become gemm consumers.
// ============================================================================
__global__ void __launch_bounds__(256, 2) __cluster_dims__(4, 1, 1)
rnn_then_consume(const float* __restrict__ ba, float* __restrict__ C)
{
    extern __shared__ __align__(1024) char smem[];
    const int bid = blockIdx.x;
    const int tid = threadIdx.x;

    {
        float2* wsp = (float2*)smem;            // [k2*64 + jl], k2=0..127
        float2* hb  = (float2*)smem + RNN_W_F2; // [(buf*4 + rq)*256 + col]
        const uint32_t hb_addr = smem_u32(hb);

        const int rq   = tid >> 6;              // rowpair 0..3
        const int jl   = tid & 63;
        const uint32_t rank = bid & 3;
        const int jg   = rank * 64 + jl;        // global output column
        const int b0   = (bid >> 2) * 8;        // 8 batch rows per cluster

        for (int i = tid; i < RNN_W_F2; i += 256) {
            int k2 = i >> 6, j = i & 63;
            int jgl = rank * 64 + j;
            wsp[i] = make_float2(g_WT[(2 * k2) * HH + jgl],
                                 g_WT[(2 * k2 + 1) * HH + jgl]);
        }
        for (int i = tid; i < 4 * 256; i += 256) hb[i] = make_float2(0.f, 0.f);

        asm volatile("barrier.cluster.arrive.aligned;" ::: "memory");
        asm volatile("barrier.cluster.wait.aligned;" ::: "memory");

        const int r0 = b0 + 2 * rq;
        const float* x0p = g_xin + (size_t)r0 * SS * HH + jg;
        const float* x1p = g_xin + (size_t)(r0 + 1) * SS * HH + jg;
        __half* a0p = g_A2 + (size_t)r0 * 512 + jg;        // + t*BB*512
        __half* a1p = g_A2 + (size_t)(r0 + 1) * 512 + jg;

        const float2* wp = wsp + jl;
        const uint32_t p1 = rank ^ 1, p2 = rank ^ 2, p3 = rank ^ 3;

        float xa = x0p[0], xb = x1p[0];
        int cur = 0;
        for (int t = 0; t < SS; ++t) {
            double acc_e = pk2(xa, xb);
            double acc_o = 0.0;
            if (t + 1 < SS) {
                xa = x0p[(size_t)(t + 1) * HH];
                xb = x1p[(size_t)(t + 1) * HH];
            }

            const double2* hc = (const double2*)(hb + (cur * 4 + rq) * 256);
#pragma unroll 8
            for (int k2 = 0; k2 < 128; ++k2) {
                float2 wv  = wp[k2 * 64];
                double2 h2 = hc[k2];
                ffma2(acc_e, dup2(wv.x), h2.x);
                ffma2(acc_o, dup2(wv.y), h2.y);
            }

            float2 f = unpk(fadd2(acc_e, acc_o));
            float h0 = tanhf(f.x), h1 = tanhf(f.y);

            const int nxt = cur ^ 1;
            const long long hp = __double_as_longlong(pk2(h0, h1));
            uint32_t loc = hb_addr + (uint32_t)(((nxt * 4 + rq) * 256 + jg) * 8);
            asm volatile("st.shared.b64 [%0], %1;" :: "r"(loc), "l"(hp) : "memory");
            asm volatile(
                "{\n\t.reg .b32 ra;\n\t"
                "mapa.shared::cluster.u32 ra, %0, %1;\n\t"
                "st.shared::cluster.b64 [ra], %2;\n\t"
                "mapa.shared::cluster.u32 ra, %0, %3;\n\t"
                "st.shared::cluster.b64 [ra], %2;\n\t"
                "mapa.shared::cluster.u32 ra, %0, %4;\n\t"
                "st.shared::cluster.b64 [ra], %2;\n\t}"
                :: "r"(loc), "r"(p1), "l"(hp), "r"(p2), "r"(p3) : "memory");

            store_split(a0p + (size_t)t * (BB * 512), h0);
            store_split(a1p + (size_t)t * (BB * 512), h1);

            asm volatile("barrier.cluster.arrive.aligned;" ::: "memory");
            asm volatile("barrier.cluster.wait.aligned;" ::: "memory");
            if (tid == 0) red_release(&g_prog[t]);
            cur = nxt;
        }
    }
    __syncthreads();
    // Scan done: convert this CTA into a gemm consumer (reuses smem).
    consume_tiles(ba, C, smem, tid);
}

// ============================================================================
// Pure consumer kernel (no cluster -> full scheduling flexibility)
// ============================================================================
__global__ void __launch_bounds__(256, 2)
gemm_consume(const float* __restrict__ ba, float* __restrict__ C)
{
    extern __shared__ __align__(1024) char smem[];
    consume_tiles(ba, C, smem, threadIdx.x);
}

// ============================================================================
extern "C" void kernel_launch(void* const* d_in, const int* in_sizes, int n_in,
                              void* d_out, int out_size)
{
    const int*   x     = (const int*)  d_in[0];
    const float* emb   = (const float*)d_in[1];
    const float* W_ih  = (const float*)d_in[2];
    const float* W_hh  = (const float*)d_in[3];
    const float* b_ih  = (const float*)d_in[4];
    const float* b_hh  = (const float*)d_in[5];
    const float* W_aff = (const float*)d_in[6];
    const float* b_aff = (const float*)d_in[7];
    float* out = (float*)d_out;

    static cudaStream_t s2 = nullptr;
    static cudaEvent_t evA = nullptr, evB = nullptr;
    if (s2 == nullptr) {
        cudaStreamCreateWithFlags(&s2, cudaStreamNonBlocking);
        cudaEventCreateWithFlags(&evA, cudaEventDisableTiming);
        cudaEventCreateWithFlags(&evB, cudaEventDisableTiming);
        cudaFuncSetAttribute(rnn_then_consume,
                             cudaFuncAttributeMaxDynamicSharedMemorySize, SMEM_TILES);
        cudaFuncSetAttribute(gemm_consume,
                             cudaFuncAttributeMaxDynamicSharedMemorySize, SMEM_TILES);
    }

    prep<<<NB_PREP, 256>>>(x, emb, W_ih, b_ih, b_hh, W_hh, W_aff);

    // fork: consumers run concurrently with the rnn producer kernel
    cudaEventRecord(evA, 0);
    cudaStreamWaitEvent(s2, evA, 0);

    rnn_then_consume<<<NB_RNN, 256, SMEM_TILES>>>(b_aff, out);          // stream 0
    gemm_consume<<<NB_GEMM, 256, SMEM_TILES, s2>>>(b_aff, out);         // stream s2

    // join
    cudaEventRecord(evB, s2);
    cudaStreamWaitEvent(0, evB, 0);
}